// round 1
// baseline (speedup 1.0000x reference)
#include <cuda_runtime.h>
#include <math.h>

#define HH 512
#define WW 512
#define NG 10000
#define NVIEWS 4
#define PATCH_HALF 20   // off = -20 .. 19

__global__ void zero_out_kernel(float4* out, int n4) {
    int i = blockIdx.x * blockDim.x + threadIdx.x;
    int stride = gridDim.x * blockDim.x;
    for (; i < n4; i += stride) out[i] = make_float4(0.f, 0.f, 0.f, 0.f);
}

__global__ void splat_kernel(
    const float* __restrict__ poses,      // (4,4,4)
    const float* __restrict__ K,          // (3,3)
    const float* __restrict__ means,      // (N,3)
    const float* __restrict__ log_scales, // (N,3)
    const float* __restrict__ quats,      // (N,4)
    const float* __restrict__ shs,        // (N,3,16)
    const float* __restrict__ opac,       // (N,1)
    float* __restrict__ out)              // (4,512,512,3)
{
    int gid = blockIdx.x * blockDim.x + threadIdx.x;
    if (gid >= NVIEWS * NG) return;
    int view = gid / NG;
    int n    = gid - view * NG;

    // ---- per-gaussian data ----
    float mx = means[n * 3 + 0];
    float my = means[n * 3 + 1];
    float mz = means[n * 3 + 2];

    float s0 = expf(log_scales[n * 3 + 0]);
    float s1 = expf(log_scales[n * 3 + 1]);
    float s2 = expf(log_scales[n * 3 + 2]);

    float qw = quats[n * 4 + 0];
    float qx = quats[n * 4 + 1];
    float qy = quats[n * 4 + 2];
    float qz = quats[n * 4 + 3];

    // rows 0 and 1 of the quaternion rotation matrix
    float R00 = 1.f - 2.f * (qy * qy + qz * qz);
    float R01 = 2.f * (qx * qy - qw * qz);
    float R02 = 2.f * (qx * qz + qw * qy);
    float R10 = 2.f * (qx * qy + qw * qz);
    float R11 = 1.f - 2.f * (qx * qx + qz * qz);
    float R12 = 2.f * (qy * qz - qw * qx);

    // 2x2 upper-left block of cov = R diag(s) R^T
    float a = s0 * R00 * R00 + s1 * R01 * R01 + s2 * R02 * R02;
    float b = s0 * R00 * R10 + s1 * R01 * R11 + s2 * R02 * R12;
    float d = s0 * R10 * R10 + s1 * R11 * R11 + s2 * R12 * R12;
    float det = a * d - b * b;
    float invdet = 1.f / det;
    float iA = d * invdet;    // inv[0][0]
    float iB = -b * invdet;   // inv[0][1] == inv[1][0]
    float iC = a * invdet;    // inv[1][1]

    // weighted color: sigmoid(opacity) * sigmoid(shs[:,c,0])
    float op = 1.f / (1.f + expf(-opac[n]));
    float w0 = op / (1.f + expf(-shs[n * 48 + 0 * 16]));
    float w1 = op / (1.f + expf(-shs[n * 48 + 1 * 16]));
    float w2 = op / (1.f + expf(-shs[n * 48 + 2 * 16]));

    // ---- per-view projection ----
    const float* P = poses + view * 16;
    float pcx = P[0] * mx + P[1] * my + P[2]  * mz + P[3];
    float pcy = P[4] * mx + P[5] * my + P[6]  * mz + P[7];
    float pcz = P[8] * mx + P[9] * my + P[10] * mz + P[11];

    if (!(pcz >= 0.1f)) return;

    float ppx = K[0] * pcx + K[1] * pcy + K[2] * pcz;
    float ppy = K[3] * pcx + K[4] * pcy + K[5] * pcz;
    float ppz = K[6] * pcx + K[7] * pcy + K[8] * pcz;

    float zd  = ppz + 1e-8f;
    float uvx = ppx / zd;
    float uvy = ppy / zd;

    // valid <=> trunc(uv) in [0, 512)
    if (!(uvx > -1.f && uvx < (float)WW && uvy > -1.f && uvy < (float)HH)) return;
    int u = (int)uvx;   // trunc toward zero; u,v in [0,511]
    int v = (int)uvy;

    // Conservative ellipse bounding box: g > 0.001 requires q < 2*ln(1000)=13.8155.
    // |px| <= sqrt(Q*cov_xx), |py| <= sqrt(Q*cov_yy). Use Q=14.2 margin; the
    // exact reference test (g > 0.001f) is applied per pixel inside the box.
    const float QM = 14.2f;
    float rx = sqrtf(QM * a);
    float ry = sqrtf(QM * d);

    float fracx = uvx - (float)u;
    float fracy = uvy - (float)v;

    int ox_lo = (int)ceilf(fracx - rx);
    int ox_hi = (int)floorf(fracx + rx);
    int oy_lo = (int)ceilf(fracy - ry);
    int oy_hi = (int)floorf(fracy + ry);

    // patch window: off in [-20, 19]; in-bounds: 0 <= u+ox < 512
    ox_lo = max(ox_lo, max(-PATCH_HALF, -u));
    ox_hi = min(ox_hi, min(PATCH_HALF - 1, WW - 1 - u));
    oy_lo = max(oy_lo, max(-PATCH_HALF, -v));
    oy_hi = min(oy_hi, min(PATCH_HALF - 1, HH - 1 - v));

    float* img = out + (size_t)view * HH * WW * 3;

    for (int oy = oy_lo; oy <= oy_hi; ++oy) {
        int yy = v + oy;
        float py = (float)yy - uvy;
        float t1 = iB * py;          // for 2*B*px*py term
        float t2 = iC * py * py;
        float* row = img + (size_t)yy * WW * 3;
        for (int ox = ox_lo; ox <= ox_hi; ++ox) {
            int xx = u + ox;
            float px = (float)xx - uvx;
            float q = iA * px * px + 2.f * t1 * px + t2;
            float expo = -0.5f * q;
            expo = fminf(expo, 0.f);
            expo = fmaxf(expo, -10.f);
            float g = expf(expo);
            if (g > 0.001f) {
                float* pix = row + (size_t)xx * 3;
                atomicAdd(pix + 0, g * w0);
                atomicAdd(pix + 1, g * w1);
                atomicAdd(pix + 2, g * w2);
            }
        }
    }
}

extern "C" void kernel_launch(void* const* d_in, const int* in_sizes, int n_in,
                              void* d_out, int out_size) {
    const float* poses      = (const float*)d_in[0];
    const float* intr       = (const float*)d_in[1];
    const float* means      = (const float*)d_in[2];
    const float* log_scales = (const float*)d_in[3];
    const float* quats      = (const float*)d_in[4];
    const float* shs        = (const float*)d_in[5];
    const float* opac       = (const float*)d_in[6];
    float* out = (float*)d_out;

    int n4 = out_size / 4;   // out_size = 4*512*512*3, divisible by 4
    zero_out_kernel<<<(n4 + 1023) / 1024, 256>>>((float4*)out, n4);

    int total = NVIEWS * NG;
    splat_kernel<<<(total + 255) / 256, 256>>>(
        poses, intr, means, log_scales, quats, shs, opac, out);
}

// round 2
// speedup vs baseline: 1.2569x; 1.2569x over previous
#include <cuda_runtime.h>
#include <math.h>

#define HH 512
#define WW 512
#define NG 10000
#define NVIEWS 4
#define PATCH_HALF 20   // off = -20 .. 19
#define TPG 8           // threads cooperating per (view, gaussian)

__global__ void zero_out_kernel(float4* out, int n4) {
    int i = blockIdx.x * blockDim.x + threadIdx.x;
    int stride = gridDim.x * blockDim.x;
    for (; i < n4; i += stride) out[i] = make_float4(0.f, 0.f, 0.f, 0.f);
}

__global__ void __launch_bounds__(256) splat_kernel(
    const float* __restrict__ poses,      // (4,4,4)
    const float* __restrict__ K,          // (3,3)
    const float* __restrict__ means,      // (N,3)
    const float* __restrict__ log_scales, // (N,3)
    const float* __restrict__ quats,      // (N,4)
    const float* __restrict__ shs,        // (N,3,16)
    const float* __restrict__ opac,       // (N,1)
    float* __restrict__ out)              // (4,512,512,3)
{
    int gid  = blockIdx.x * blockDim.x + threadIdx.x;
    int work = gid >> 3;          // / TPG
    int lane = gid & (TPG - 1);
    if (work >= NVIEWS * NG) return;
    int view = work / NG;
    int n    = work - view * NG;

    // ---- per-gaussian data (8 threads read the same addrs -> L1 broadcast) ----
    float mx = means[n * 3 + 0];
    float my = means[n * 3 + 1];
    float mz = means[n * 3 + 2];

    float s0 = expf(log_scales[n * 3 + 0]);
    float s1 = expf(log_scales[n * 3 + 1]);
    float s2 = expf(log_scales[n * 3 + 2]);

    float qw = quats[n * 4 + 0];
    float qx = quats[n * 4 + 1];
    float qy = quats[n * 4 + 2];
    float qz = quats[n * 4 + 3];

    // rows 0 and 1 of the quaternion rotation matrix
    float R00 = 1.f - 2.f * (qy * qy + qz * qz);
    float R01 = 2.f * (qx * qy - qw * qz);
    float R02 = 2.f * (qx * qz + qw * qy);
    float R10 = 2.f * (qx * qy + qw * qz);
    float R11 = 1.f - 2.f * (qx * qx + qz * qz);
    float R12 = 2.f * (qy * qz - qw * qx);

    // 2x2 upper-left block of cov = R diag(s) R^T
    float a = s0 * R00 * R00 + s1 * R01 * R01 + s2 * R02 * R02;
    float b = s0 * R00 * R10 + s1 * R01 * R11 + s2 * R02 * R12;
    float d = s0 * R10 * R10 + s1 * R11 * R11 + s2 * R12 * R12;
    float det = a * d - b * b;
    float invdet = 1.f / det;
    float iA = d * invdet;    // inv[0][0]
    float iB = -b * invdet;   // inv[0][1] == inv[1][0]
    float iC = a * invdet;    // inv[1][1]

    // weighted color: sigmoid(opacity) * sigmoid(shs[:,c,0])
    float op = 1.f / (1.f + expf(-opac[n]));
    float w0 = op / (1.f + expf(-shs[n * 48 + 0 * 16]));
    float w1 = op / (1.f + expf(-shs[n * 48 + 1 * 16]));
    float w2 = op / (1.f + expf(-shs[n * 48 + 2 * 16]));

    // ---- per-view projection ----
    const float* P = poses + view * 16;
    float pcx = P[0] * mx + P[1] * my + P[2]  * mz + P[3];
    float pcy = P[4] * mx + P[5] * my + P[6]  * mz + P[7];
    float pcz = P[8] * mx + P[9] * my + P[10] * mz + P[11];

    if (!(pcz >= 0.1f)) return;

    float ppx = K[0] * pcx + K[1] * pcy + K[2] * pcz;
    float ppy = K[3] * pcx + K[4] * pcy + K[5] * pcz;
    float ppz = K[6] * pcx + K[7] * pcy + K[8] * pcz;

    float zd  = ppz + 1e-8f;
    float uvx = ppx / zd;
    float uvy = ppy / zd;

    // valid <=> trunc(uv) in [0, 512)
    if (!(uvx > -1.f && uvx < (float)WW && uvy > -1.f && uvy < (float)HH)) return;
    int u = (int)uvx;   // trunc toward zero; u,v in [0,511]
    int v = (int)uvy;

    // Conservative ellipse bounding box: g > 0.001 requires q < 2*ln(1000)=13.8155.
    // |px| <= sqrt(Q*cov_xx), |py| <= sqrt(Q*cov_yy). Use Q=14.2 margin; the
    // exact reference test (g > 0.001f) is applied per pixel inside the box.
    const float QM = 14.2f;
    float rx = sqrtf(QM * a);
    float ry = sqrtf(QM * d);

    float fracx = uvx - (float)u;
    float fracy = uvy - (float)v;

    int ox_lo = (int)ceilf(fracx - rx);
    int ox_hi = (int)floorf(fracx + rx);
    int oy_lo = (int)ceilf(fracy - ry);
    int oy_hi = (int)floorf(fracy + ry);

    // patch window: off in [-20, 19]; in-bounds: 0 <= u+ox < 512
    ox_lo = max(ox_lo, max(-PATCH_HALF, -u));
    ox_hi = min(ox_hi, min(PATCH_HALF - 1, WW - 1 - u));
    oy_lo = max(oy_lo, max(-PATCH_HALF, -v));
    oy_hi = min(oy_hi, min(PATCH_HALF - 1, HH - 1 - v));

    int nx = ox_hi - ox_lo + 1;
    int ny = oy_hi - oy_lo + 1;
    if (nx <= 0 || ny <= 0) return;
    int cnt = nx * ny;

    float* img = out + (size_t)view * HH * WW * 3;

    // each of the TPG threads takes every TPG-th pixel of the bbox
    for (int p = lane; p < cnt; p += TPG) {
        int oyi = p / nx;
        int oxi = p - oyi * nx;
        int yy = v + oy_lo + oyi;
        int xx = u + ox_lo + oxi;
        float py = (float)yy - uvy;
        float px = (float)xx - uvx;
        float q = iA * px * px + 2.f * iB * px * py + iC * py * py;
        float expo = -0.5f * q;
        expo = fminf(expo, 0.f);
        expo = fmaxf(expo, -10.f);
        float g = expf(expo);
        if (g > 0.001f) {
            float* pix = img + ((size_t)yy * WW + xx) * 3;
            atomicAdd(pix + 0, g * w0);
            atomicAdd(pix + 1, g * w1);
            atomicAdd(pix + 2, g * w2);
        }
    }
}

extern "C" void kernel_launch(void* const* d_in, const int* in_sizes, int n_in,
                              void* d_out, int out_size) {
    const float* poses      = (const float*)d_in[0];
    const float* intr       = (const float*)d_in[1];
    const float* means      = (const float*)d_in[2];
    const float* log_scales = (const float*)d_in[3];
    const float* quats      = (const float*)d_in[4];
    const float* shs        = (const float*)d_in[5];
    const float* opac       = (const float*)d_in[6];
    float* out = (float*)d_out;

    int n4 = out_size / 4;   // out_size = 4*512*512*3, divisible by 4
    zero_out_kernel<<<(n4 + 1023) / 1024, 256>>>((float4*)out, n4);

    int total = NVIEWS * NG * TPG;
    splat_kernel<<<(total + 255) / 256, 256>>>(
        poses, intr, means, log_scales, quats, shs, opac, out);
}

// round 3
// speedup vs baseline: 1.2898x; 1.0261x over previous
#include <cuda_runtime.h>
#include <math.h>

#define HH 512
#define WW 512
#define NG 10000
#define NVIEWS 4
#define PATCH_HALF 20   // off = -20 .. 19
#define TPG 8           // threads cooperating per (view, gaussian)
#define NWORK (NVIEWS * NG)

// per-(view,gaussian) record: 3 x float4
//  rec[0] = {uvx, uvy, iA, iB}
//  rec[1] = {iC, w0, w1, w2}
//  rec[2] = {x0(int bits), y0(int bits), nx(int bits), cnt(int bits)}
__device__ float4 g_rec[NWORK * 3];

__global__ void __launch_bounds__(256) setup_kernel(
    const float* __restrict__ poses,      // (4,4,4)
    const float* __restrict__ K,          // (3,3)
    const float* __restrict__ means,      // (N,3)
    const float* __restrict__ log_scales, // (N,3)
    const float* __restrict__ quats,      // (N,4)
    const float* __restrict__ shs,        // (N,3,16)
    const float* __restrict__ opac,       // (N,1)
    float4* __restrict__ out4, int n4)    // fused zeroing of output
{
    int tid = blockIdx.x * blockDim.x + threadIdx.x;
    int nth = gridDim.x * blockDim.x;

    // fused: zero the output image (grid-stride)
    for (int i = tid; i < n4; i += nth) out4[i] = make_float4(0.f, 0.f, 0.f, 0.f);

    int work = tid;
    if (work >= NWORK) return;
    int view = work / NG;
    int n    = work - view * NG;

    float4 r0, r1, r2;
    r2.w = __int_as_float(0);   // cnt = 0 default (invalid)
    r2.x = r2.y = r2.z = __int_as_float(0);
    r0 = make_float4(0.f, 0.f, 0.f, 0.f);
    r1 = make_float4(0.f, 0.f, 0.f, 0.f);

    float mx = means[n * 3 + 0];
    float my = means[n * 3 + 1];
    float mz = means[n * 3 + 2];

    const float* P = poses + view * 16;
    float pcx = P[0] * mx + P[1] * my + P[2]  * mz + P[3];
    float pcy = P[4] * mx + P[5] * my + P[6]  * mz + P[7];
    float pcz = P[8] * mx + P[9] * my + P[10] * mz + P[11];

    bool ok = (pcz >= 0.1f);

    float ppx = K[0] * pcx + K[1] * pcy + K[2] * pcz;
    float ppy = K[3] * pcx + K[4] * pcy + K[5] * pcz;
    float ppz = K[6] * pcx + K[7] * pcy + K[8] * pcz;

    float zd  = ppz + 1e-8f;
    float uvx = fdividef(ppx, zd);
    float uvy = fdividef(ppy, zd);

    ok = ok && (uvx > -1.f && uvx < (float)WW && uvy > -1.f && uvy < (float)HH);

    if (ok) {
        int u = (int)uvx;   // trunc; in [0,511]
        int v = (int)uvy;

        float s0 = __expf(log_scales[n * 3 + 0]);
        float s1 = __expf(log_scales[n * 3 + 1]);
        float s2 = __expf(log_scales[n * 3 + 2]);

        float qw = quats[n * 4 + 0];
        float qx = quats[n * 4 + 1];
        float qy = quats[n * 4 + 2];
        float qz = quats[n * 4 + 3];

        float R00 = 1.f - 2.f * (qy * qy + qz * qz);
        float R01 = 2.f * (qx * qy - qw * qz);
        float R02 = 2.f * (qx * qz + qw * qy);
        float R10 = 2.f * (qx * qy + qw * qz);
        float R11 = 1.f - 2.f * (qx * qx + qz * qz);
        float R12 = 2.f * (qy * qz - qw * qx);

        float a = s0 * R00 * R00 + s1 * R01 * R01 + s2 * R02 * R02;
        float b = s0 * R00 * R10 + s1 * R01 * R11 + s2 * R02 * R12;
        float d = s0 * R10 * R10 + s1 * R11 * R11 + s2 * R12 * R12;
        float det = a * d - b * b;
        float invdet = fdividef(1.f, det);
        float iA = d * invdet;
        float iB = -b * invdet;
        float iC = a * invdet;

        float op = fdividef(1.f, 1.f + __expf(-opac[n]));
        float w0 = fdividef(op, 1.f + __expf(-shs[n * 48 + 0 * 16]));
        float w1 = fdividef(op, 1.f + __expf(-shs[n * 48 + 1 * 16]));
        float w2 = fdividef(op, 1.f + __expf(-shs[n * 48 + 2 * 16]));

        // conservative ellipse bbox; exact g>0.001 test is reapplied per pixel
        const float QM = 14.2f;
        float rx = sqrtf(QM * a);
        float ry = sqrtf(QM * d);

        float fracx = uvx - (float)u;
        float fracy = uvy - (float)v;

        int ox_lo = (int)ceilf(fracx - rx);
        int ox_hi = (int)floorf(fracx + rx);
        int oy_lo = (int)ceilf(fracy - ry);
        int oy_hi = (int)floorf(fracy + ry);

        ox_lo = max(ox_lo, max(-PATCH_HALF, -u));
        ox_hi = min(ox_hi, min(PATCH_HALF - 1, WW - 1 - u));
        oy_lo = max(oy_lo, max(-PATCH_HALF, -v));
        oy_hi = min(oy_hi, min(PATCH_HALF - 1, HH - 1 - v));

        int nx = ox_hi - ox_lo + 1;
        int ny = oy_hi - oy_lo + 1;
        int cnt = (nx > 0 && ny > 0) ? nx * ny : 0;

        r0 = make_float4(uvx, uvy, iA, iB);
        r1 = make_float4(iC, w0, w1, w2);
        r2.x = __int_as_float(u + ox_lo);
        r2.y = __int_as_float(v + oy_lo);
        r2.z = __int_as_float(nx);
        r2.w = __int_as_float(cnt);
    }

    g_rec[work * 3 + 0] = r0;
    g_rec[work * 3 + 1] = r1;
    g_rec[work * 3 + 2] = r2;
}

__global__ void __launch_bounds__(256) splat_kernel(float* __restrict__ out)
{
    int gid  = blockIdx.x * blockDim.x + threadIdx.x;
    int work = gid >> 3;          // / TPG
    int lane = gid & (TPG - 1);
    if (work >= NWORK) return;

    float4 r2 = g_rec[work * 3 + 2];
    int cnt = __float_as_int(r2.w);
    if (lane >= cnt) return;

    float4 r0 = g_rec[work * 3 + 0];
    float4 r1 = g_rec[work * 3 + 1];

    float uvx = r0.x, uvy = r0.y, iA = r0.z, iB = r0.w;
    float iC  = r1.x, w0 = r1.y, w1 = r1.z, w2 = r1.w;
    int x0 = __float_as_int(r2.x);
    int y0 = __float_as_int(r2.y);
    int nx = __float_as_int(r2.z);

    int view = work / NG;
    float* img = out + (size_t)view * HH * WW * 3;

    for (int p = lane; p < cnt; p += TPG) {
        int oyi = p / nx;
        int oxi = p - oyi * nx;
        int yy = y0 + oyi;
        int xx = x0 + oxi;
        float py = (float)yy - uvy;
        float px = (float)xx - uvx;
        float q = iA * px * px + 2.f * iB * px * py + iC * py * py;
        float expo = -0.5f * q;
        expo = fminf(expo, 0.f);
        expo = fmaxf(expo, -10.f);
        float g = __expf(expo);
        if (g > 0.001f) {
            float* pix = img + ((size_t)yy * WW + xx) * 3;
            atomicAdd(pix + 0, g * w0);
            atomicAdd(pix + 1, g * w1);
            atomicAdd(pix + 2, g * w2);
        }
    }
}

extern "C" void kernel_launch(void* const* d_in, const int* in_sizes, int n_in,
                              void* d_out, int out_size) {
    const float* poses      = (const float*)d_in[0];
    const float* intr       = (const float*)d_in[1];
    const float* means      = (const float*)d_in[2];
    const float* log_scales = (const float*)d_in[3];
    const float* quats      = (const float*)d_in[4];
    const float* shs        = (const float*)d_in[5];
    const float* opac       = (const float*)d_in[6];
    float* out = (float*)d_out;

    int n4 = out_size / 4;
    int blocksA = (NWORK + 255) / 256;     // 157 blocks: setup + fused zeroing
    setup_kernel<<<blocksA, 256>>>(poses, intr, means, log_scales, quats, shs, opac,
                                   (float4*)out, n4);

    int total = NWORK * TPG;
    splat_kernel<<<(total + 255) / 256, 256>>>(out);
}